// round 1
// baseline (speedup 1.0000x reference)
#include <cuda_runtime.h>
#include <cuda_bf16.h>

#define S_LEN 4096
#define HID   768
#define NH    12
#define HD    64

// Scratch: Q/K/V in head-major layout [head][s][64]
__device__ float g_Q[NH * S_LEN * HD];
__device__ float g_K[NH * S_LEN * HD];
__device__ float g_V[NH * S_LEN * HD];

// ---------------------------------------------------------------------------
// Kernel 1: QKV projection.  out = X @ W + b, scattered to [head][s][d].
// Grid: (HID/64, S_LEN/64, 3), block 256.  BM=BN=64, BK=16, 4x4 microtile.
// ---------------------------------------------------------------------------
__global__ __launch_bounds__(256) void qkv_gemm(
    const float* __restrict__ X,
    const float* __restrict__ Wq, const float* __restrict__ bq,
    const float* __restrict__ Wk, const float* __restrict__ bk,
    const float* __restrict__ Wv, const float* __restrict__ bv)
{
    const float* W;  const float* bias;  float* out;
    if (blockIdx.z == 0)      { W = Wq; bias = bq; out = g_Q; }
    else if (blockIdx.z == 1) { W = Wk; bias = bk; out = g_K; }
    else                      { W = Wv; bias = bv; out = g_V; }

    __shared__ float As[64][17];   // [BM][BK+1]
    __shared__ float Bs[16][65];   // [BK][BN+1]

    const int tid = threadIdx.x;
    const int tx  = tid & 15;      // 0..15 -> N
    const int ty  = tid >> 4;      // 0..15 -> M
    const int row0 = blockIdx.y * 64;   // along S
    const int col0 = blockIdx.x * 64;   // along HID

    float acc[4][4] = {};

    for (int k0 = 0; k0 < HID; k0 += 16) {
        // A tile: 64x16
        #pragma unroll
        for (int i = tid; i < 64 * 16; i += 256) {
            int r = i >> 4, c = i & 15;
            As[r][c] = X[(row0 + r) * HID + k0 + c];
        }
        // W tile: 16x64
        #pragma unroll
        for (int i = tid; i < 16 * 64; i += 256) {
            int r = i >> 6, c = i & 63;
            Bs[r][c] = W[(k0 + r) * HID + col0 + c];
        }
        __syncthreads();

        #pragma unroll
        for (int kk = 0; kk < 16; kk++) {
            float a[4], b[4];
            #pragma unroll
            for (int i = 0; i < 4; i++) a[i] = As[ty * 4 + i][kk];
            #pragma unroll
            for (int j = 0; j < 4; j++) b[j] = Bs[kk][tx * 4 + j];
            #pragma unroll
            for (int i = 0; i < 4; i++)
                #pragma unroll
                for (int j = 0; j < 4; j++)
                    acc[i][j] += a[i] * b[j];
        }
        __syncthreads();
    }

    // Scatter to head-major scratch
    #pragma unroll
    for (int i = 0; i < 4; i++) {
        int s = row0 + ty * 4 + i;
        #pragma unroll
        for (int j = 0; j < 4; j++) {
            int n    = col0 + tx * 4 + j;
            int head = n >> 6;
            int d    = n & 63;
            out[(head * S_LEN + s) * HD + d] = acc[i][j] + bias[n];
        }
    }
}

// ---------------------------------------------------------------------------
// Kernel 2: flash attention, fp32. One CTA per (q-tile of 64 rows, head).
// Block 256 threads as 16x16; each thread: 4 rows x 4 cols microtiles.
// Dynamic smem: Qs, Ks, Vs, Ps each 64x65 floats = 66560 B total.
// ---------------------------------------------------------------------------
#define TPAD 65
#define FLASH_SMEM (4 * 64 * TPAD * sizeof(float))

__global__ __launch_bounds__(256) void flash_attn(float* __restrict__ out)
{
    extern __shared__ float smem[];
    float* Qs = smem;                  // [64][65]
    float* Ks = Qs + 64 * TPAD;        // [64][65]
    float* Vs = Ks + 64 * TPAD;        // [64][65]
    float* Ps = Vs + 64 * TPAD;        // [64][65]

    const int head = blockIdx.y;
    const int q0   = blockIdx.x * 64;

    const float* Qg = g_Q + (head * S_LEN + q0) * HD;
    const float* Kg = g_K + head * S_LEN * HD;
    const float* Vg = g_V + head * S_LEN * HD;

    const int tid = threadIdx.x;
    const int tx  = tid & 15;   // cols
    const int ty  = tid >> 4;   // rows
    const float scale = 0.125f; // 1/sqrt(64)

    // Load Q tile, pre-scaled
    #pragma unroll
    for (int i = tid; i < 64 * HD; i += 256) {
        int r = i >> 6, c = i & 63;
        Qs[r * TPAD + c] = Qg[r * HD + c] * scale;
    }

    float m[4], l[4], o[4][4];
    #pragma unroll
    for (int i = 0; i < 4; i++) {
        m[i] = -1e30f; l[i] = 0.0f;
        #pragma unroll
        for (int j = 0; j < 4; j++) o[i][j] = 0.0f;
    }
    __syncthreads();

    for (int k0 = 0; k0 < S_LEN; k0 += 64) {
        // Load K,V tiles (coalesced: 64 contiguous floats/row)
        #pragma unroll
        for (int i = tid; i < 64 * HD; i += 256) {
            int r = i >> 6, c = i & 63;
            Ks[r * TPAD + c] = Kg[(k0 + r) * HD + c];
            Vs[r * TPAD + c] = Vg[(k0 + r) * HD + c];
        }
        __syncthreads();

        // S = Q K^T  (64x64x64)
        float s[4][4] = {};
        #pragma unroll
        for (int d = 0; d < HD; d++) {
            float a[4], b[4];
            #pragma unroll
            for (int i = 0; i < 4; i++) a[i] = Qs[(ty * 4 + i) * TPAD + d];
            #pragma unroll
            for (int j = 0; j < 4; j++) b[j] = Ks[(tx * 4 + j) * TPAD + d];
            #pragma unroll
            for (int i = 0; i < 4; i++)
                #pragma unroll
                for (int j = 0; j < 4; j++)
                    s[i][j] += a[i] * b[j];
        }

        // Online softmax per row (row spread over 16 lanes sharing ty)
        #pragma unroll
        for (int i = 0; i < 4; i++) {
            float mx = fmaxf(fmaxf(s[i][0], s[i][1]), fmaxf(s[i][2], s[i][3]));
            #pragma unroll
            for (int off = 1; off < 16; off <<= 1)
                mx = fmaxf(mx, __shfl_xor_sync(0xffffffffu, mx, off));
            float mnew  = fmaxf(m[i], mx);
            float alpha = __expf(m[i] - mnew);
            float rowsum = 0.0f;
            #pragma unroll
            for (int j = 0; j < 4; j++) {
                s[i][j] = __expf(s[i][j] - mnew);
                rowsum += s[i][j];
            }
            #pragma unroll
            for (int off = 1; off < 16; off <<= 1)
                rowsum += __shfl_xor_sync(0xffffffffu, rowsum, off);
            l[i] = l[i] * alpha + rowsum;
            m[i] = mnew;
            #pragma unroll
            for (int j = 0; j < 4; j++) o[i][j] *= alpha;
            #pragma unroll
            for (int j = 0; j < 4; j++)
                Ps[(ty * 4 + i) * TPAD + tx * 4 + j] = s[i][j];
        }
        __syncthreads();

        // O += P @ V  (64x64x64)
        #pragma unroll
        for (int c = 0; c < 64; c++) {
            float p[4], v[4];
            #pragma unroll
            for (int i = 0; i < 4; i++) p[i] = Ps[(ty * 4 + i) * TPAD + c];
            #pragma unroll
            for (int j = 0; j < 4; j++) v[j] = Vs[c * TPAD + tx * 4 + j];
            #pragma unroll
            for (int i = 0; i < 4; i++)
                #pragma unroll
                for (int j = 0; j < 4; j++)
                    o[i][j] += p[i] * v[j];
        }
        __syncthreads();
    }

    // Normalize + write: out[s][head*64 + d]
    #pragma unroll
    for (int i = 0; i < 4; i++) {
        float inv = 1.0f / l[i];
        int r = q0 + ty * 4 + i;
        #pragma unroll
        for (int j = 0; j < 4; j++)
            out[r * HID + head * HD + tx * 4 + j] = o[i][j] * inv;
    }
}

// ---------------------------------------------------------------------------
extern "C" void kernel_launch(void* const* d_in, const int* in_sizes, int n_in,
                              void* d_out, int out_size)
{
    const float* X  = (const float*)d_in[0];
    const float* Wq = (const float*)d_in[1];
    const float* bq = (const float*)d_in[2];
    const float* Wk = (const float*)d_in[3];
    const float* bk = (const float*)d_in[4];
    const float* Wv = (const float*)d_in[5];
    const float* bv = (const float*)d_in[6];
    float* out = (float*)d_out;

    // Allow >48KB dynamic smem for the attention kernel (idempotent).
    cudaFuncSetAttribute(flash_attn, cudaFuncAttributeMaxDynamicSharedMemorySize,
                         (int)FLASH_SMEM);

    dim3 g1(HID / 64, S_LEN / 64, 3);
    qkv_gemm<<<g1, 256>>>(X, Wq, bq, Wk, bk, Wv, bv);

    dim3 g2(S_LEN / 64, NH);
    flash_attn<<<g2, 256, FLASH_SMEM>>>(out);
}

// round 2
// speedup vs baseline: 1.2670x; 1.2670x over previous
#include <cuda_runtime.h>
#include <cuda_bf16.h>

#define S_LEN 4096
#define HID   768
#define NH    12
#define HD    64

typedef unsigned long long u64;

// Packed f32x2 helpers (Blackwell dual-fp32 path, FFMA2 in SASS)
__device__ __forceinline__ u64 bc2(float x) {
    u64 r; asm("mov.b64 %0, {%1, %1};" : "=l"(r) : "f"(x)); return r;
}
__device__ __forceinline__ u64 pk2(float lo, float hi) {
    u64 r; asm("mov.b64 %0, {%1, %2};" : "=l"(r) : "f"(lo), "f"(hi)); return r;
}
__device__ __forceinline__ void up2(float& lo, float& hi, u64 v) {
    asm("mov.b64 {%0, %1}, %2;" : "=f"(lo), "=f"(hi) : "l"(v));
}
__device__ __forceinline__ void ffma2(u64& d, u64 a, u64 b) {
    asm("fma.rn.f32x2 %0, %1, %2, %0;" : "+l"(d) : "l"(a), "l"(b));
}
__device__ __forceinline__ u64 fmul2(u64 a, u64 b) {
    u64 d; asm("mul.rn.f32x2 %0, %1, %2;" : "=l"(d) : "l"(a), "l"(b)); return d;
}

// Scratch: Q/K/V head-major [head][s][64]
__device__ float g_Q[NH * S_LEN * HD];
__device__ float g_K[NH * S_LEN * HD];
__device__ float g_V[NH * S_LEN * HD];

// ---------------------------------------------------------------------------
// Kernel 1: QKV projection, packed f32x2. Tile 128x64, BK=16, 128 threads,
// 8x8 microtile per thread (rows scalar-broadcast, col-pairs packed).
// ---------------------------------------------------------------------------
__global__ __launch_bounds__(128) void qkv_gemm(
    const float* __restrict__ X,
    const float* __restrict__ Wq, const float* __restrict__ bq,
    const float* __restrict__ Wk, const float* __restrict__ bk,
    const float* __restrict__ Wv, const float* __restrict__ bv)
{
    const float* W;  const float* bias;  float* out;
    if (blockIdx.z == 0)      { W = Wq; bias = bq; out = g_Q; }
    else if (blockIdx.z == 1) { W = Wk; bias = bk; out = g_K; }
    else                      { W = Wv; bias = bv; out = g_V; }

    __shared__ float Xs[128][17];   // [BM][BK+1]
    __shared__ float Ws[16][66];    // [BK][BN+2]

    const int tid = threadIdx.x;
    const int tx  = tid & 7;        // 8 col-groups of 8
    const int ty  = tid >> 3;       // 16 row-groups of 8
    const int row0 = blockIdx.y * 128;
    const int col0 = blockIdx.x * 64;

    u64 acc[8][4];
    #pragma unroll
    for (int i = 0; i < 8; i++)
        #pragma unroll
        for (int j = 0; j < 4; j++) acc[i][j] = 0ULL;

    for (int k0 = 0; k0 < HID; k0 += 16) {
        // X tile 128x16 (512 float4)
        #pragma unroll
        for (int it = 0; it < 4; it++) {
            int idx = tid + it * 128;
            int r = idx >> 2, c4 = (idx & 3) << 2;
            float4 v = *(const float4*)&X[(row0 + r) * HID + k0 + c4];
            Xs[r][c4] = v.x; Xs[r][c4+1] = v.y; Xs[r][c4+2] = v.z; Xs[r][c4+3] = v.w;
        }
        // W tile 16x64 (256 float4)
        #pragma unroll
        for (int it = 0; it < 2; it++) {
            int idx = tid + it * 128;
            int r = idx >> 4, c4 = (idx & 15) << 2;
            float4 v = *(const float4*)&W[(k0 + r) * HID + col0 + c4];
            Ws[r][c4] = v.x; Ws[r][c4+1] = v.y; Ws[r][c4+2] = v.z; Ws[r][c4+3] = v.w;
        }
        __syncthreads();

        #pragma unroll
        for (int kk = 0; kk < 16; kk++) {
            u64 b[4];
            #pragma unroll
            for (int j = 0; j < 4; j++)
                b[j] = *(const u64*)&Ws[kk][tx * 8 + 2 * j];
            #pragma unroll
            for (int i = 0; i < 8; i++) {
                u64 a = bc2(Xs[ty * 8 + i][kk]);
                #pragma unroll
                for (int j = 0; j < 4; j++) ffma2(acc[i][j], a, b[j]);
            }
        }
        __syncthreads();
    }

    // Epilogue: + bias, scatter to head-major [head][s][d]
    #pragma unroll
    for (int i = 0; i < 8; i++) {
        int s = row0 + ty * 8 + i;
        #pragma unroll
        for (int j = 0; j < 4; j++) {
            int n = col0 + tx * 8 + 2 * j;
            int head = n >> 6, d = n & 63;
            float lo, hi; up2(lo, hi, acc[i][j]);
            float2 v = make_float2(lo + bias[n], hi + bias[n + 1]);
            *(float2*)&out[(head * S_LEN + s) * HD + d] = v;
        }
    }
}

// ---------------------------------------------------------------------------
// Kernel 2: flash attention, packed f32x2. Q tile 128, KV tile 64,
// 128 threads (tx=8 col-groups, ty=16 row-groups), 8x8 microtiles.
// Row dimension packed in pairs; QsT/PsT stored d-major (transposed).
// ---------------------------------------------------------------------------
#define QPAD 130
#define KPAD 66
// QsT[64][130] + KsT[64][66] + Vs[64][66] + PsT[64][130]
#define FLASH_SMEM ((64*QPAD + 64*KPAD + 64*KPAD + 64*QPAD) * sizeof(float))

__global__ __launch_bounds__(128) void flash_attn(float* __restrict__ out)
{
    extern __shared__ float sm[];
    float* QsT = sm;                    // [d][r]  64 x 130
    float* KsT = QsT + 64 * QPAD;       // [d][c]  64 x 66
    float* Vs  = KsT + 64 * KPAD;       // [c][d]  64 x 66
    float* PsT = Vs  + 64 * KPAD;       // [c][r]  64 x 130

    const int head = blockIdx.y;
    const int q0   = blockIdx.x * 128;
    const int tid  = threadIdx.x;
    const int tx   = tid & 7;           // col group (8 cols)
    const int ty   = tid >> 3;          // row group (8 rows)

    const float* Qg = g_Q + (head * S_LEN + q0) * HD;
    const float* Kg = g_K + head * S_LEN * HD;
    const float* Vg = g_V + head * S_LEN * HD;

    // Load Q transposed + pre-scaled: QsT[d][r] = Q[r][d] * 0.125
    #pragma unroll
    for (int it = 0; it < 16; it++) {
        int idx4 = tid + it * 128;
        int r = idx4 >> 4, d4 = (idx4 & 15) << 2;
        float4 v = *(const float4*)&Qg[r * HD + d4];
        QsT[(d4 + 0) * QPAD + r] = v.x * 0.125f;
        QsT[(d4 + 1) * QPAD + r] = v.y * 0.125f;
        QsT[(d4 + 2) * QPAD + r] = v.z * 0.125f;
        QsT[(d4 + 3) * QPAD + r] = v.w * 0.125f;
    }

    u64 o[4][8];                        // rows packed in pairs (rp), 8 d-cols
    #pragma unroll
    for (int rp = 0; rp < 4; rp++)
        #pragma unroll
        for (int j = 0; j < 8; j++) o[rp][j] = 0ULL;
    float m[8], l[8];
    #pragma unroll
    for (int i = 0; i < 8; i++) { m[i] = -1e30f; l[i] = 0.0f; }

    __syncthreads();

    for (int k0 = 0; k0 < S_LEN; k0 += 64) {
        // Load K transposed (scalar scatter), V straight (u64 copies)
        #pragma unroll
        for (int it = 0; it < 32; it++) {
            int idx = tid + it * 128;
            int c = idx >> 6, d = idx & 63;
            KsT[d * KPAD + c] = Kg[(k0 + c) * HD + d];
        }
        #pragma unroll
        for (int it = 0; it < 16; it++) {
            int idx = tid + it * 128;
            int c = idx >> 5, d2 = idx & 31;
            *(u64*)&Vs[c * KPAD + 2 * d2] = *(const u64*)&Vg[(k0 + c) * HD + 2 * d2];
        }
        __syncthreads();

        // S = Q K^T : s_p[col j][row-pair rp]
        u64 s_p[8][4];
        #pragma unroll
        for (int j = 0; j < 8; j++)
            #pragma unroll
            for (int rp = 0; rp < 4; rp++) s_p[j][rp] = 0ULL;

        for (int d = 0; d < HD; d++) {
            u64 q[4];
            #pragma unroll
            for (int rp = 0; rp < 4; rp++)
                q[rp] = *(const u64*)&QsT[d * QPAD + ty * 8 + 2 * rp];
            #pragma unroll
            for (int j = 0; j < 8; j++) {
                u64 kb = bc2(KsT[d * KPAD + tx * 8 + j]);
                #pragma unroll
                for (int rp = 0; rp < 4; rp++) ffma2(s_p[j][rp], q[rp], kb);
            }
        }

        // Online softmax (rows spread over 8 tx lanes)
        #pragma unroll
        for (int rp = 0; rp < 4; rp++) {
            int i0 = 2 * rp, i1 = 2 * rp + 1;
            float e0[8], e1[8];
            float mx0 = -1e30f, mx1 = -1e30f;
            #pragma unroll
            for (int j = 0; j < 8; j++) {
                up2(e0[j], e1[j], s_p[j][rp]);
                mx0 = fmaxf(mx0, e0[j]); mx1 = fmaxf(mx1, e1[j]);
            }
            #pragma unroll
            for (int off = 1; off < 8; off <<= 1) {
                mx0 = fmaxf(mx0, __shfl_xor_sync(0xffffffffu, mx0, off));
                mx1 = fmaxf(mx1, __shfl_xor_sync(0xffffffffu, mx1, off));
            }
            float mn0 = fmaxf(m[i0], mx0), mn1 = fmaxf(m[i1], mx1);
            float a0 = __expf(m[i0] - mn0), a1 = __expf(m[i1] - mn1);
            float s0 = 0.0f, s1 = 0.0f;
            #pragma unroll
            for (int j = 0; j < 8; j++) {
                e0[j] = __expf(e0[j] - mn0); s0 += e0[j];
                e1[j] = __expf(e1[j] - mn1); s1 += e1[j];
            }
            #pragma unroll
            for (int off = 1; off < 8; off <<= 1) {
                s0 += __shfl_xor_sync(0xffffffffu, s0, off);
                s1 += __shfl_xor_sync(0xffffffffu, s1, off);
            }
            l[i0] = l[i0] * a0 + s0;  m[i0] = mn0;
            l[i1] = l[i1] * a1 + s1;  m[i1] = mn1;
            u64 ap = pk2(a0, a1);
            #pragma unroll
            for (int j = 0; j < 8; j++) o[rp][j] = fmul2(o[rp][j], ap);
            #pragma unroll
            for (int j = 0; j < 8; j++)
                *(u64*)&PsT[(tx * 8 + j) * QPAD + ty * 8 + 2 * rp] = pk2(e0[j], e1[j]);
        }
        __syncthreads();

        // O += P @ V
        for (int c = 0; c < 64; c++) {
            u64 p[4];
            #pragma unroll
            for (int rp = 0; rp < 4; rp++)
                p[rp] = *(const u64*)&PsT[c * QPAD + ty * 8 + 2 * rp];
            #pragma unroll
            for (int j = 0; j < 8; j++) {
                u64 vb = bc2(Vs[c * KPAD + tx * 8 + j]);
                #pragma unroll
                for (int rp = 0; rp < 4; rp++) ffma2(o[rp][j], p[rp], vb);
            }
        }
        __syncthreads();
    }

    // Epilogue: normalize, write out[s][head*64 + d] (vectorized per row)
    #pragma unroll
    for (int rp = 0; rp < 4; rp++) {
        float inv0 = 1.0f / l[2 * rp], inv1 = 1.0f / l[2 * rp + 1];
        float v0[8], v1[8];
        #pragma unroll
        for (int j = 0; j < 8; j++) {
            float lo, hi; up2(lo, hi, o[rp][j]);
            v0[j] = lo * inv0; v1[j] = hi * inv1;
        }
        int r0 = q0 + ty * 8 + 2 * rp;
        int col = head * HD + tx * 8;
        *(float4*)&out[r0 * HID + col]           = make_float4(v0[0], v0[1], v0[2], v0[3]);
        *(float4*)&out[r0 * HID + col + 4]       = make_float4(v0[4], v0[5], v0[6], v0[7]);
        *(float4*)&out[(r0 + 1) * HID + col]     = make_float4(v1[0], v1[1], v1[2], v1[3]);
        *(float4*)&out[(r0 + 1) * HID + col + 4] = make_float4(v1[4], v1[5], v1[6], v1[7]);
    }
}

// ---------------------------------------------------------------------------
extern "C" void kernel_launch(void* const* d_in, const int* in_sizes, int n_in,
                              void* d_out, int out_size)
{
    const float* X  = (const float*)d_in[0];
    const float* Wq = (const float*)d_in[1];
    const float* bq = (const float*)d_in[2];
    const float* Wk = (const float*)d_in[3];
    const float* bk = (const float*)d_in[4];
    const float* Wv = (const float*)d_in[5];
    const float* bv = (const float*)d_in[6];
    float* out = (float*)d_out;

    cudaFuncSetAttribute(flash_attn, cudaFuncAttributeMaxDynamicSharedMemorySize,
                         (int)FLASH_SMEM);

    dim3 g1(HID / 64, S_LEN / 128, 3);
    qkv_gemm<<<g1, 128>>>(X, Wq, bq, Wk, bk, Wv, bv);

    dim3 g2(S_LEN / 128, NH);
    flash_attn<<<g2, 128, FLASH_SMEM>>>(out);
}